// round 3
// baseline (speedup 1.0000x reference)
#include <cuda_runtime.h>
#include <cstddef>

#define B_TOTAL 32768
#define T_SEQ   7
#define D_IN    40
#define H_DIM   64
#define FC_DIM  32
#define BLK     224
#define NBLK    147   // ceil(32768/224)

// Inter-layer scratch: layer-0 hidden states [B][T][H]
__device__ __align__(16) float g_h1[(size_t)B_TOTAL * T_SEQ * H_DIM];

__device__ __forceinline__ float sigf(float x) {
    // 1/(1+e^-x) via MUFU.EX2 + MUFU.RCP
    return __fdividef(1.0f, 1.0f + __expf(-x));
}
__device__ __forceinline__ float tanhf_fast(float x) {
    // 2/(1+e^-2x) - 1 ; exact at saturation (inf handled by rcp -> 0)
    return __fdividef(2.0f, 1.0f + __expf(-2.0f * x)) - 1.0f;
}

// One LSTM layer for one batch element (one thread).
// KIN: input width (40 for layer0, 64 for layer1). WRITE_SCR: dump h_t to scratch.
template <int KIN, bool WRITE_SCR>
__device__ __forceinline__ void lstm_phase(
    const float* __restrict__ in_base,   // thread's input base; step t at +t*KIN
    float* __restrict__ scr_base,        // thread's scratch base; step t at +t*64
    const float* __restrict__ sWin,      // [256, KIN] row-major in smem
    const float* __restrict__ sWhh,      // [256, 64]  row-major in smem
    const float* __restrict__ sBias,     // [256] (b_ih+b_hh)
    float h_out[H_DIM])
{
    float h[H_DIM];          // register-resident (all compile-time indexed)
    float c[H_DIM];          // dynamically indexed -> local mem (cheap)
    float hn[H_DIM];         // dynamically written -> local mem

#pragma unroll
    for (int k = 0; k < H_DIM; k++) h[k] = 0.0f;
    for (int j = 0; j < H_DIM; j++) { c[j] = 0.0f; hn[j] = 0.0f; }

    for (int t = 0; t < T_SEQ; t++) {
        float inv[KIN];
        const float4* ip = reinterpret_cast<const float4*>(in_base + t * KIN);
#pragma unroll
        for (int q = 0; q < KIN / 4; q++) {
            float4 v = ip[q];
            inv[4*q+0] = v.x; inv[4*q+1] = v.y; inv[4*q+2] = v.z; inv[4*q+3] = v.w;
        }

        for (int j = 0; j < H_DIM; j++) {   // rolled: keeps I-footprint small
            float ai = sBias[j];
            float af = sBias[64 + j];
            float ag = sBias[128 + j];
            float ao = sBias[192 + j];

            const float4* wi = reinterpret_cast<const float4*>(sWin + (0   + j) * KIN);
            const float4* wf = reinterpret_cast<const float4*>(sWin + (64  + j) * KIN);
            const float4* wg = reinterpret_cast<const float4*>(sWin + (128 + j) * KIN);
            const float4* wo = reinterpret_cast<const float4*>(sWin + (192 + j) * KIN);
#pragma unroll
            for (int q = 0; q < KIN / 4; q++) {
                float4 a = wi[q], b4 = wf[q], g4 = wg[q], o4 = wo[q];
                ai = fmaf(inv[4*q+0], a.x, ai);  ai = fmaf(inv[4*q+1], a.y, ai);
                ai = fmaf(inv[4*q+2], a.z, ai);  ai = fmaf(inv[4*q+3], a.w, ai);
                af = fmaf(inv[4*q+0], b4.x, af); af = fmaf(inv[4*q+1], b4.y, af);
                af = fmaf(inv[4*q+2], b4.z, af); af = fmaf(inv[4*q+3], b4.w, af);
                ag = fmaf(inv[4*q+0], g4.x, ag); ag = fmaf(inv[4*q+1], g4.y, ag);
                ag = fmaf(inv[4*q+2], g4.z, ag); ag = fmaf(inv[4*q+3], g4.w, ag);
                ao = fmaf(inv[4*q+0], o4.x, ao); ao = fmaf(inv[4*q+1], o4.y, ao);
                ao = fmaf(inv[4*q+2], o4.z, ao); ao = fmaf(inv[4*q+3], o4.w, ao);
            }

            const float4* ri = reinterpret_cast<const float4*>(sWhh + (0   + j) * H_DIM);
            const float4* rf = reinterpret_cast<const float4*>(sWhh + (64  + j) * H_DIM);
            const float4* rg = reinterpret_cast<const float4*>(sWhh + (128 + j) * H_DIM);
            const float4* ro = reinterpret_cast<const float4*>(sWhh + (192 + j) * H_DIM);
#pragma unroll
            for (int q = 0; q < H_DIM / 4; q++) {
                float4 a = ri[q], b4 = rf[q], g4 = rg[q], o4 = ro[q];
                ai = fmaf(h[4*q+0], a.x, ai);  ai = fmaf(h[4*q+1], a.y, ai);
                ai = fmaf(h[4*q+2], a.z, ai);  ai = fmaf(h[4*q+3], a.w, ai);
                af = fmaf(h[4*q+0], b4.x, af); af = fmaf(h[4*q+1], b4.y, af);
                af = fmaf(h[4*q+2], b4.z, af); af = fmaf(h[4*q+3], b4.w, af);
                ag = fmaf(h[4*q+0], g4.x, ag); ag = fmaf(h[4*q+1], g4.y, ag);
                ag = fmaf(h[4*q+2], g4.z, ag); ag = fmaf(h[4*q+3], g4.w, ag);
                ao = fmaf(h[4*q+0], o4.x, ao); ao = fmaf(h[4*q+1], o4.y, ao);
                ao = fmaf(h[4*q+2], o4.z, ao); ao = fmaf(h[4*q+3], o4.w, ao);
            }

            float gi = sigf(ai);
            float gf = sigf(af);
            float gg = tanhf_fast(ag);
            float go = sigf(ao);
            float cj = fmaf(gf, c[j], gi * gg);
            c[j] = cj;
            hn[j] = go * tanhf_fast(cj);
        }

#pragma unroll
        for (int k = 0; k < H_DIM; k++) h[k] = hn[k];

        if (WRITE_SCR) {
            float4* op = reinterpret_cast<float4*>(scr_base + t * H_DIM);
#pragma unroll
            for (int q = 0; q < H_DIM / 4; q++)
                op[q] = make_float4(h[4*q], h[4*q+1], h[4*q+2], h[4*q+3]);
        }
    }
#pragma unroll
    for (int k = 0; k < H_DIM; k++) h_out[k] = h[k];
}

// smem layout (floats)
#define OFF_WIN   0
#define OFF_WHH   16384
#define OFF_BIAS  32768
#define OFF_W1    33024
#define OFF_B1    35072
#define OFF_W2    35104
#define OFF_B2    35136
#define SMEM_FLOATS 35140
#define SMEM_BYTES  (SMEM_FLOATS * 4)

__global__ void __launch_bounds__(BLK, 1)
rainfall_lstm_kernel(
    const float* __restrict__ x,
    const float* __restrict__ Wih0, const float* __restrict__ Whh0,
    const float* __restrict__ bih0, const float* __restrict__ bhh0,
    const float* __restrict__ Wih1, const float* __restrict__ Whh1,
    const float* __restrict__ bih1, const float* __restrict__ bhh1,
    const float* __restrict__ W1, const float* __restrict__ b1,
    const float* __restrict__ W2, const float* __restrict__ b2,
    float* __restrict__ out)
{
    extern __shared__ float sm[];
    float* sWin  = sm + OFF_WIN;
    float* sWhh  = sm + OFF_WHH;
    float* sBias = sm + OFF_BIAS;
    float* sW1   = sm + OFF_W1;
    float* sB1   = sm + OFF_B1;
    float* sW2   = sm + OFF_W2;
    float* sB2   = sm + OFF_B2;

    const int tid = threadIdx.x;
    const int b   = blockIdx.x * BLK + tid;

    // ---- Phase A: layer-0 weights -> smem ----
    for (int i = tid; i < 256 * D_IN; i += BLK) sWin[i] = Wih0[i];
    for (int i = tid; i < 256 * H_DIM; i += BLK) sWhh[i] = Whh0[i];
    for (int i = tid; i < 256; i += BLK) sBias[i] = bih0[i] + bhh0[i];
    __syncthreads();

    float hfin[H_DIM];
    if (b < B_TOTAL) {
        lstm_phase<D_IN, true>(
            x + (size_t)b * (T_SEQ * D_IN),
            g_h1 + (size_t)b * (T_SEQ * H_DIM),
            sWin, sWhh, sBias, hfin);
    }
    __syncthreads();

    // ---- Phase B: layer-1 + FC weights -> smem ----
    for (int i = tid; i < 256 * H_DIM; i += BLK) sWin[i] = Wih1[i];
    for (int i = tid; i < 256 * H_DIM; i += BLK) sWhh[i] = Whh1[i];
    for (int i = tid; i < 256; i += BLK) sBias[i] = bih1[i] + bhh1[i];
    for (int i = tid; i < FC_DIM * H_DIM; i += BLK) sW1[i] = W1[i];
    if (tid < FC_DIM) { sB1[tid] = b1[tid]; sW2[tid] = W2[tid]; }
    if (tid == 0) sB2[0] = b2[0];
    __syncthreads();

    if (b < B_TOTAL) {
        lstm_phase<H_DIM, false>(
            g_h1 + (size_t)b * (T_SEQ * H_DIM),
            nullptr,
            sWin, sWhh, sBias, hfin);

        // FC head: relu(h @ W1^T + b1) @ W2^T + b2
        float acc_out = sB2[0];
#pragma unroll
        for (int r = 0; r < FC_DIM; r++) {
            float a = sB1[r];
            const float4* w = reinterpret_cast<const float4*>(sW1 + r * H_DIM);
#pragma unroll
            for (int q = 0; q < H_DIM / 4; q++) {
                float4 wv = w[q];
                a = fmaf(hfin[4*q+0], wv.x, a);
                a = fmaf(hfin[4*q+1], wv.y, a);
                a = fmaf(hfin[4*q+2], wv.z, a);
                a = fmaf(hfin[4*q+3], wv.w, a);
            }
            a = fmaxf(a, 0.0f);
            acc_out = fmaf(a, sW2[r], acc_out);
        }
        out[b] = acc_out;
    }
}

extern "C" void kernel_launch(void* const* d_in, const int* in_sizes, int n_in,
                              void* d_out, int out_size)
{
    (void)in_sizes; (void)n_in; (void)out_size;
    const float* x    = (const float*)d_in[0];
    const float* Wih0 = (const float*)d_in[1];
    const float* Whh0 = (const float*)d_in[2];
    const float* bih0 = (const float*)d_in[3];
    const float* bhh0 = (const float*)d_in[4];
    const float* Wih1 = (const float*)d_in[5];
    const float* Whh1 = (const float*)d_in[6];
    const float* bih1 = (const float*)d_in[7];
    const float* bhh1 = (const float*)d_in[8];
    const float* W1   = (const float*)d_in[9];
    const float* b1   = (const float*)d_in[10];
    const float* W2   = (const float*)d_in[11];
    const float* b2   = (const float*)d_in[12];
    float* out = (float*)d_out;

    // Idempotent, non-stream-ordered host attribute set: safe under graph
    // capture, no static guard (harness forbids call-count-dependent paths).
    cudaFuncSetAttribute(rainfall_lstm_kernel,
                         cudaFuncAttributeMaxDynamicSharedMemorySize,
                         SMEM_BYTES);

    rainfall_lstm_kernel<<<NBLK, BLK, SMEM_BYTES>>>(
        x, Wih0, Whh0, bih0, bhh0, Wih1, Whh1, bih1, bhh1,
        W1, b1, W2, b2, out);
}

// round 4
// speedup vs baseline: 1.2531x; 1.2531x over previous
#include <cuda_runtime.h>
#include <cstddef>

#define B_TOTAL 32768
#define T_SEQ   7
#define D_IN    40
#define H_DIM   64
#define FC_DIM  32
#define ROWS    128          // batch rows per block
#define BLKT    256          // threads per block
#define NBLK    (B_TOTAL / ROWS)   // 256
#define WSTR    260          // padded stride (floats) for transposed weight rows

typedef unsigned long long u64;

// Layer-0 hidden states, [T][H][B] so store + reload are coalesced.
__device__ __align__(16) float g_h1[(size_t)T_SEQ * H_DIM * B_TOTAL];

// ---------------- smem layout (floats) ----------------
#define OFF_WIH  0                       // [<=64][WSTR] transposed W_ih
#define OFF_WHH  (OFF_WIH + 64*WSTR)     // [64][WSTR]   transposed W_hh
#define OFF_X    (OFF_WHH + 64*WSTR)     // [<=64][128]  input vectors, k-major
#define OFF_H    (OFF_X  + 64*ROWS)      // [64][128]    hidden state, k-major
#define OFF_BIAS (OFF_H  + 64*ROWS)      // [256]
#define OFF_W1   (OFF_BIAS + 256)        // [32][64]
#define OFF_B1   (OFF_W1 + FC_DIM*H_DIM)
#define OFF_W2   (OFF_B1 + FC_DIM)
#define OFF_B2   (OFF_W2 + FC_DIM)
#define SMEM_FLOATS (OFF_B2 + 1)
#define SMEM_BYTES  (SMEM_FLOATS * 4)    // ~208 KB

// ---------------- packed-f32 helpers ----------------
__device__ __forceinline__ u64 dup2(float x) {
    u64 r; asm("mov.b64 %0, {%1, %1};" : "=l"(r) : "f"(x)); return r;
}
__device__ __forceinline__ u64 ffma2(u64 a, u64 b, u64 c) {
    u64 d; asm("fma.rn.f32x2 %0, %1, %2, %3;" : "=l"(d) : "l"(a), "l"(b), "l"(c)); return d;
}
__device__ __forceinline__ float2 unpk(u64 a) {
    float2 f; asm("mov.b64 {%0, %1}, %2;" : "=f"(f.x), "=f"(f.y) : "l"(a)); return f;
}
__device__ __forceinline__ float sigf(float x) {
    return __fdividef(1.0f, 1.0f + __expf(-x));
}
__device__ __forceinline__ float tanhf_fast(float x) {
    return __fdividef(2.0f, 1.0f + __expf(-2.0f * x)) - 1.0f;
}

// ---------------- register-tiled GEMM over one K-range ----------------
// acc[r*8 + g*2 + h] accumulates (rows rm+r) x (cols g*64 + ct4 + 2h, +1) packed.
template <int K>
__device__ __forceinline__ void gemm_k(const float* __restrict__ sV,
                                       const float* __restrict__ sW,
                                       int rm, int ct4, u64 acc[64])
{
#pragma unroll 2
    for (int k = 0; k < K; k++) {
        const float4 v0 = *reinterpret_cast<const float4*>(sV + k * ROWS + rm);
        const float4 v1 = *reinterpret_cast<const float4*>(sV + k * ROWS + rm + 4);
        u64 d[8];
        d[0] = dup2(v0.x); d[1] = dup2(v0.y); d[2] = dup2(v0.z); d[3] = dup2(v0.w);
        d[4] = dup2(v1.x); d[5] = dup2(v1.y); d[6] = dup2(v1.z); d[7] = dup2(v1.w);

        const float* wr = sW + k * WSTR + ct4;
        ulonglong2 w0 = *reinterpret_cast<const ulonglong2*>(wr);        // gate i
        ulonglong2 w1 = *reinterpret_cast<const ulonglong2*>(wr + 64);   // gate f
        ulonglong2 w2 = *reinterpret_cast<const ulonglong2*>(wr + 128);  // gate g
        ulonglong2 w3 = *reinterpret_cast<const ulonglong2*>(wr + 192);  // gate o
        u64 wp[8] = { w0.x, w0.y, w1.x, w1.y, w2.x, w2.y, w3.x, w3.y };

#pragma unroll
        for (int r = 0; r < 8; r++)
#pragma unroll
            for (int p = 0; p < 8; p++)
                acc[r * 8 + p] = ffma2(d[r], wp[p], acc[r * 8 + p]);
    }
}

// ---------------- one LSTM layer for the block's 128 rows ----------------
template <int KIN, bool PHASE_A>
__device__ __forceinline__ void lstm_block_phase(
    const float* __restrict__ gin,      // PHASE_A: x base pointer; else unused
    float* __restrict__ sWih, float* __restrict__ sWhh,
    float* __restrict__ sX,  float* __restrict__ sH,
    const float* __restrict__ sBias,
    int tid, int b0)
{
    const int ct  = tid >> 4;       // 0..15 col tile
    const int rt  = tid & 15;       // 0..15 row tile
    const int rm  = rt * 8;
    const int ct4 = ct * 4;

    u64 bp[8];
#pragma unroll
    for (int p = 0; p < 8; p++) {
        int g = p >> 1, h = p & 1;
        bp[p] = *reinterpret_cast<const u64*>(sBias + g * 64 + ct4 + 2 * h);
    }

    float creg[32];
#pragma unroll
    for (int i = 0; i < 32; i++) creg[i] = 0.0f;

    for (int t = 0; t < T_SEQ; t++) {
        // ---- stage this step's input vectors into sX (k-major over rows) ----
        if (PHASE_A) {
            int row = tid >> 1, half = tid & 1;  // 20 floats each
            const float4* src = reinterpret_cast<const float4*>(
                gin + (size_t)(b0 + row) * (T_SEQ * D_IN) + t * D_IN + half * 20);
#pragma unroll
            for (int q = 0; q < 5; q++) {
                float4 v = src[q];
                int d = half * 20 + q * 4;
                sX[(d + 0) * ROWS + row] = v.x;
                sX[(d + 1) * ROWS + row] = v.y;
                sX[(d + 2) * ROWS + row] = v.z;
                sX[(d + 3) * ROWS + row] = v.w;
            }
        } else {
            int l = tid * 32;
            int j = l >> 7, r0 = l & 127;
            const float4* src = reinterpret_cast<const float4*>(
                g_h1 + ((size_t)t * H_DIM + j) * B_TOTAL + b0 + r0);
            float4* dst = reinterpret_cast<float4*>(sX + j * ROWS + r0);
#pragma unroll
            for (int q = 0; q < 8; q++) dst[q] = src[q];
        }
        __syncthreads();

        // ---- GEMM: gates = bias + x@WihT + h@WhhT ----
        u64 acc[64];
#pragma unroll
        for (int r = 0; r < 8; r++)
#pragma unroll
            for (int p = 0; p < 8; p++) acc[r * 8 + p] = bp[p];

        gemm_k<KIN>(sX, sWih, rm, ct4, acc);
        gemm_k<H_DIM>(sH, sWhh, rm, ct4, acc);
        __syncthreads();   // all reads of sX/sH complete

        // ---- elementwise cell update; write new h into sH ----
#pragma unroll
        for (int r = 0; r < 8; r++) {
#pragma unroll
            for (int h = 0; h < 2; h++) {
                float2 iv = unpk(acc[r * 8 + 0 + h]);
                float2 fv = unpk(acc[r * 8 + 2 + h]);
                float2 gv = unpk(acc[r * 8 + 4 + h]);
                float2 ov = unpk(acc[r * 8 + 6 + h]);
                {
                    const int jj = 2 * h;
                    float ig = sigf(iv.x), fg = sigf(fv.x);
                    float gg = tanhf_fast(gv.x), og = sigf(ov.x);
                    float cn = fmaf(fg, creg[r * 4 + jj], ig * gg);
                    creg[r * 4 + jj] = cn;
                    sH[(ct4 + jj) * ROWS + rm + r] = og * tanhf_fast(cn);
                }
                {
                    const int jj = 2 * h + 1;
                    float ig = sigf(iv.y), fg = sigf(fv.y);
                    float gg = tanhf_fast(gv.y), og = sigf(ov.y);
                    float cn = fmaf(fg, creg[r * 4 + jj], ig * gg);
                    creg[r * 4 + jj] = cn;
                    sH[(ct4 + jj) * ROWS + rm + r] = og * tanhf_fast(cn);
                }
            }
        }
        __syncthreads();   // sH complete

        if (PHASE_A) {
            // coalesced copy-out of h_t to global scratch [t][j][b]
            int l = tid * 32;
            int j = l >> 7, r0 = l & 127;
            float4* dst = reinterpret_cast<float4*>(
                g_h1 + ((size_t)t * H_DIM + j) * B_TOTAL + b0 + r0);
            const float4* src = reinterpret_cast<const float4*>(sH + j * ROWS + r0);
#pragma unroll
            for (int q = 0; q < 8; q++) dst[q] = src[q];
        }
    }
}

__global__ void __launch_bounds__(BLKT, 1)
rainfall_lstm_kernel(
    const float* __restrict__ x,
    const float* __restrict__ Wih0, const float* __restrict__ Whh0,
    const float* __restrict__ bih0, const float* __restrict__ bhh0,
    const float* __restrict__ Wih1, const float* __restrict__ Whh1,
    const float* __restrict__ bih1, const float* __restrict__ bhh1,
    const float* __restrict__ W1, const float* __restrict__ b1,
    const float* __restrict__ W2, const float* __restrict__ b2,
    float* __restrict__ out)
{
    extern __shared__ float sm[];
    float* sWih  = sm + OFF_WIH;
    float* sWhh  = sm + OFF_WHH;
    float* sX    = sm + OFF_X;
    float* sH    = sm + OFF_H;
    float* sBias = sm + OFF_BIAS;
    float* sW1   = sm + OFF_W1;
    float* sB1   = sm + OFF_B1;
    float* sW2   = sm + OFF_W2;
    float* sB2   = sm + OFF_B2;

    const int tid = threadIdx.x;
    const int b0  = blockIdx.x * ROWS;

    // ---- Phase A setup: transpose layer-0 weights into [k][256] (padded) ----
    for (int e = tid; e < 256 * D_IN; e += BLKT) {
        int c = e / D_IN, k = e % D_IN;
        sWih[k * WSTR + c] = Wih0[e];
    }
    for (int e = tid; e < 256 * H_DIM; e += BLKT) {
        int c = e / H_DIM, k = e % H_DIM;
        sWhh[k * WSTR + c] = Whh0[e];
    }
    for (int i = tid; i < 256; i += BLKT) sBias[i] = bih0[i] + bhh0[i];
    for (int i = tid; i < H_DIM * ROWS; i += BLKT) sH[i] = 0.0f;
    __syncthreads();

    lstm_block_phase<D_IN, true>(x, sWih, sWhh, sX, sH, sBias, tid, b0);
    __syncthreads();

    // ---- Phase B setup: layer-1 + FC weights ----
    for (int e = tid; e < 256 * H_DIM; e += BLKT) {
        int c = e / H_DIM, k = e % H_DIM;
        sWih[k * WSTR + c] = Wih1[e];
    }
    for (int e = tid; e < 256 * H_DIM; e += BLKT) {
        int c = e / H_DIM, k = e % H_DIM;
        sWhh[k * WSTR + c] = Whh1[e];
    }
    for (int i = tid; i < 256; i += BLKT) sBias[i] = bih1[i] + bhh1[i];
    for (int i = tid; i < H_DIM * ROWS; i += BLKT) sH[i] = 0.0f;
    for (int i = tid; i < FC_DIM * H_DIM; i += BLKT) sW1[i] = W1[i];
    if (tid < FC_DIM) { sB1[tid] = b1[tid]; sW2[tid] = W2[tid]; }
    if (tid == 0) sB2[0] = b2[0];
    __syncthreads();

    lstm_block_phase<H_DIM, false>(nullptr, sWih, sWhh, sX, sH, sBias, tid, b0);

    // ---- FC head: one thread per row ----
    if (tid < ROWS) {
        const int row = tid;
        float hv[H_DIM];
#pragma unroll
        for (int j = 0; j < H_DIM; j++) hv[j] = sH[j * ROWS + row];

        float o = sB2[0];
        for (int r = 0; r < FC_DIM; r++) {
            float a = sB1[r];
            const float* w = sW1 + r * H_DIM;
#pragma unroll
            for (int j = 0; j < H_DIM; j++) a = fmaf(hv[j], w[j], a);
            o = fmaf(fmaxf(a, 0.0f), sW2[r], o);
        }
        out[b0 + row] = o;
    }
}

extern "C" void kernel_launch(void* const* d_in, const int* in_sizes, int n_in,
                              void* d_out, int out_size)
{
    (void)in_sizes; (void)n_in; (void)out_size;
    const float* x    = (const float*)d_in[0];
    const float* Wih0 = (const float*)d_in[1];
    const float* Whh0 = (const float*)d_in[2];
    const float* bih0 = (const float*)d_in[3];
    const float* bhh0 = (const float*)d_in[4];
    const float* Wih1 = (const float*)d_in[5];
    const float* Whh1 = (const float*)d_in[6];
    const float* bih1 = (const float*)d_in[7];
    const float* bhh1 = (const float*)d_in[8];
    const float* W1   = (const float*)d_in[9];
    const float* b1   = (const float*)d_in[10];
    const float* W2   = (const float*)d_in[11];
    const float* b2   = (const float*)d_in[12];
    float* out = (float*)d_out;

    cudaFuncSetAttribute(rainfall_lstm_kernel,
                         cudaFuncAttributeMaxDynamicSharedMemorySize,
                         SMEM_BYTES);

    rainfall_lstm_kernel<<<NBLK, BLKT, SMEM_BYTES>>>(
        x, Wih0, Whh0, bih0, bhh0, Wih1, Whh1, bih1, bhh1,
        W1, b1, W2, b2, out);
}

// round 5
// speedup vs baseline: 1.3571x; 1.0830x over previous
#include <cuda_runtime.h>
#include <cstddef>

#define B_TOTAL 32768
#define T_SEQ   7
#define D_IN    40
#define H_DIM   64
#define FC_DIM  32
#define ROWS    128               // batch rows per block
#define BLKT    512               // threads per block
#define NBLK    (B_TOTAL / ROWS)  // 256
#define WSTR    260               // padded stride (floats) for transposed weights

typedef unsigned long long u64;

// Layer-0 hidden states, [T][H][B] so store + reload are coalesced.
__device__ __align__(16) float g_h1[(size_t)T_SEQ * H_DIM * B_TOTAL];

// ---------------- smem layout (floats) ----------------
#define OFF_WIH  0                       // [<=64][WSTR] transposed W_ih
#define OFF_WHH  (OFF_WIH + 64*WSTR)     // [64][WSTR]   transposed W_hh
#define OFF_X    (OFF_WHH + 64*WSTR)     // [<=64][128]  input vectors, k-major
#define OFF_H    (OFF_X  + 64*ROWS)      // [64][128]    hidden state, k-major
#define OFF_BIAS (OFF_H  + 64*ROWS)      // [256]
#define OFF_W1   (OFF_BIAS + 256)        // [32][64]
#define OFF_B1   (OFF_W1 + FC_DIM*H_DIM)
#define OFF_W2   (OFF_B1 + FC_DIM)
#define OFF_B2   (OFF_W2 + FC_DIM)
#define SMEM_FLOATS (OFF_B2 + 1)
#define SMEM_BYTES  (SMEM_FLOATS * 4)    // ~200 KB

// ---------------- packed-f32 helpers ----------------
__device__ __forceinline__ u64 dup2(float x) {
    u64 r; asm("mov.b64 %0, {%1, %1};" : "=l"(r) : "f"(x)); return r;
}
__device__ __forceinline__ u64 ffma2(u64 a, u64 b, u64 c) {
    u64 d; asm("fma.rn.f32x2 %0, %1, %2, %3;" : "=l"(d) : "l"(a), "l"(b), "l"(c)); return d;
}
__device__ __forceinline__ float2 unpk(u64 a) {
    float2 f; asm("mov.b64 {%0, %1}, %2;" : "=f"(f.x), "=f"(f.y) : "l"(a)); return f;
}
__device__ __forceinline__ float sigf(float x) {
    return __fdividef(1.0f, 1.0f + __expf(-x));
}
__device__ __forceinline__ float tanhf_fast(float x) {
    return __fdividef(2.0f, 1.0f + __expf(-2.0f * x)) - 1.0f;
}

// ---------------- register-tiled GEMM over one K-range ----------------
// Thread tile: 4 rows (rm..rm+3) x 16 cols (4 j-values replicated over 4 gates).
// acc[r*8 + g*2 + h] packs cols (g*64 + ct4 + 2h, +1), r=0..3.
template <int K>
__device__ __forceinline__ void gemm_k(const float* __restrict__ sV,
                                       const float* __restrict__ sW,
                                       int rm, int ct4, u64 acc[32])
{
#pragma unroll 2
    for (int k = 0; k < K; k++) {
        const float4 v = *reinterpret_cast<const float4*>(sV + k * ROWS + rm);
        u64 d0 = dup2(v.x), d1 = dup2(v.y), d2 = dup2(v.z), d3 = dup2(v.w);

        const float* wr = sW + k * WSTR + ct4;
#pragma unroll
        for (int g = 0; g < 4; g++) {
            ulonglong2 w = *reinterpret_cast<const ulonglong2*>(wr + g * 64);
            acc[0*8 + g*2 + 0] = ffma2(d0, w.x, acc[0*8 + g*2 + 0]);
            acc[0*8 + g*2 + 1] = ffma2(d0, w.y, acc[0*8 + g*2 + 1]);
            acc[1*8 + g*2 + 0] = ffma2(d1, w.x, acc[1*8 + g*2 + 0]);
            acc[1*8 + g*2 + 1] = ffma2(d1, w.y, acc[1*8 + g*2 + 1]);
            acc[2*8 + g*2 + 0] = ffma2(d2, w.x, acc[2*8 + g*2 + 0]);
            acc[2*8 + g*2 + 1] = ffma2(d2, w.y, acc[2*8 + g*2 + 1]);
            acc[3*8 + g*2 + 0] = ffma2(d3, w.x, acc[3*8 + g*2 + 0]);
            acc[3*8 + g*2 + 1] = ffma2(d3, w.y, acc[3*8 + g*2 + 1]);
        }
    }
}

// ---------------- one LSTM layer for the block's 128 rows ----------------
template <int KIN, bool PHASE_A>
__device__ __forceinline__ void lstm_block_phase(
    const float* __restrict__ gin,      // PHASE_A: x base pointer; else unused
    float* __restrict__ sWih, float* __restrict__ sWhh,
    float* __restrict__ sX,  float* __restrict__ sH,
    const float* __restrict__ sBias,
    int tid, int b0)
{
    const int ct  = tid >> 5;       // 0..15 col tile (warp-uniform)
    const int rt  = tid & 31;       // 0..31 row tile
    const int rm  = rt * 4;
    const int ct4 = ct * 4;

    float creg[16];                 // c-state: 4 rows x 4 j-values
#pragma unroll
    for (int i = 0; i < 16; i++) creg[i] = 0.0f;

    for (int t = 0; t < T_SEQ; t++) {
        // ---- stage this step's input vectors into sX (k-major over rows) ----
        if (PHASE_A) {
            if (tid < 256) {
                int row = tid >> 1, half = tid & 1;  // 20 floats each
                const float4* src = reinterpret_cast<const float4*>(
                    gin + (size_t)(b0 + row) * (T_SEQ * D_IN) + t * D_IN + half * 20);
#pragma unroll
                for (int q = 0; q < 5; q++) {
                    float4 v = src[q];
                    int d = half * 20 + q * 4;
                    sX[(d + 0) * ROWS + row] = v.x;
                    sX[(d + 1) * ROWS + row] = v.y;
                    sX[(d + 2) * ROWS + row] = v.z;
                    sX[(d + 3) * ROWS + row] = v.w;
                }
            }
        } else {
            int l = tid * 16;
            int j = l >> 7, r0 = l & 127;
            const float4* src = reinterpret_cast<const float4*>(
                g_h1 + ((size_t)t * H_DIM + j) * B_TOTAL + b0 + r0);
            float4* dst = reinterpret_cast<float4*>(sX + j * ROWS + r0);
#pragma unroll
            for (int q = 0; q < 4; q++) dst[q] = src[q];
        }
        __syncthreads();

        // ---- init accumulators from bias (broadcast LDS, no persistent regs) ----
        u64 acc[32];
#pragma unroll
        for (int p = 0; p < 8; p++) {
            int g = p >> 1, h = p & 1;
            u64 bv = *reinterpret_cast<const u64*>(sBias + g * 64 + ct4 + 2 * h);
            acc[0*8 + p] = bv; acc[1*8 + p] = bv;
            acc[2*8 + p] = bv; acc[3*8 + p] = bv;
        }

        // ---- GEMM: gates = bias + x@WihT + h@WhhT ----
        gemm_k<KIN>(sX, sWih, rm, ct4, acc);
        gemm_k<H_DIM>(sH, sWhh, rm, ct4, acc);
        __syncthreads();   // all reads of sX/sH complete

        // ---- elementwise cell update; write new h into sH ----
#pragma unroll
        for (int r = 0; r < 4; r++) {
#pragma unroll
            for (int h = 0; h < 2; h++) {
                float2 iv = unpk(acc[r * 8 + 0 + h]);
                float2 fv = unpk(acc[r * 8 + 2 + h]);
                float2 gv = unpk(acc[r * 8 + 4 + h]);
                float2 ov = unpk(acc[r * 8 + 6 + h]);
                {
                    const int jj = 2 * h;
                    float ig = sigf(iv.x), fg = sigf(fv.x);
                    float gg = tanhf_fast(gv.x), og = sigf(ov.x);
                    float cn = fmaf(fg, creg[r * 4 + jj], ig * gg);
                    creg[r * 4 + jj] = cn;
                    sH[(ct4 + jj) * ROWS + rm + r] = og * tanhf_fast(cn);
                }
                {
                    const int jj = 2 * h + 1;
                    float ig = sigf(iv.y), fg = sigf(fv.y);
                    float gg = tanhf_fast(gv.y), og = sigf(ov.y);
                    float cn = fmaf(fg, creg[r * 4 + jj], ig * gg);
                    creg[r * 4 + jj] = cn;
                    sH[(ct4 + jj) * ROWS + rm + r] = og * tanhf_fast(cn);
                }
            }
        }
        __syncthreads();   // sH complete

        if (PHASE_A) {
            // coalesced copy-out of h_t to global scratch [t][j][b]
            int l = tid * 16;
            int j = l >> 7, r0 = l & 127;
            float4* dst = reinterpret_cast<float4*>(
                g_h1 + ((size_t)t * H_DIM + j) * B_TOTAL + b0 + r0);
            const float4* src = reinterpret_cast<const float4*>(sH + j * ROWS + r0);
#pragma unroll
            for (int q = 0; q < 4; q++) dst[q] = src[q];
        }
    }
}

__global__ void __launch_bounds__(BLKT, 1)
rainfall_lstm_kernel(
    const float* __restrict__ x,
    const float* __restrict__ Wih0, const float* __restrict__ Whh0,
    const float* __restrict__ bih0, const float* __restrict__ bhh0,
    const float* __restrict__ Wih1, const float* __restrict__ Whh1,
    const float* __restrict__ bih1, const float* __restrict__ bhh1,
    const float* __restrict__ W1, const float* __restrict__ b1,
    const float* __restrict__ W2, const float* __restrict__ b2,
    float* __restrict__ out)
{
    extern __shared__ float sm[];
    float* sWih  = sm + OFF_WIH;
    float* sWhh  = sm + OFF_WHH;
    float* sX    = sm + OFF_X;
    float* sH    = sm + OFF_H;
    float* sBias = sm + OFF_BIAS;
    float* sW1   = sm + OFF_W1;
    float* sB1   = sm + OFF_B1;
    float* sW2   = sm + OFF_W2;
    float* sB2   = sm + OFF_B2;

    const int tid = threadIdx.x;
    const int b0  = blockIdx.x * ROWS;

    // ---- Phase A setup: transpose layer-0 weights into [k][256] (padded) ----
    for (int e = tid; e < 256 * D_IN; e += BLKT) {
        int c = e / D_IN, k = e % D_IN;
        sWih[k * WSTR + c] = Wih0[e];
    }
    for (int e = tid; e < 256 * H_DIM; e += BLKT) {
        int c = e / H_DIM, k = e % H_DIM;
        sWhh[k * WSTR + c] = Whh0[e];
    }
    for (int i = tid; i < 256; i += BLKT) sBias[i] = bih0[i] + bhh0[i];
    for (int i = tid; i < H_DIM * ROWS; i += BLKT) sH[i] = 0.0f;
    __syncthreads();

    lstm_block_phase<D_IN, true>(x, sWih, sWhh, sX, sH, sBias, tid, b0);
    __syncthreads();

    // ---- Phase B setup: layer-1 + FC weights ----
    for (int e = tid; e < 256 * H_DIM; e += BLKT) {
        int c = e / H_DIM, k = e % H_DIM;
        sWih[k * WSTR + c] = Wih1[e];
    }
    for (int e = tid; e < 256 * H_DIM; e += BLKT) {
        int c = e / H_DIM, k = e % H_DIM;
        sWhh[k * WSTR + c] = Whh1[e];
    }
    for (int i = tid; i < 256; i += BLKT) sBias[i] = bih1[i] + bhh1[i];
    for (int i = tid; i < H_DIM * ROWS; i += BLKT) sH[i] = 0.0f;
    for (int i = tid; i < FC_DIM * H_DIM; i += BLKT) sW1[i] = W1[i];
    if (tid < FC_DIM) { sB1[tid] = b1[tid]; sW2[tid] = W2[tid]; }
    if (tid == 0) sB2[0] = b2[0];
    __syncthreads();

    lstm_block_phase<H_DIM, false>(nullptr, sWih, sWhh, sX, sH, sBias, tid, b0);

    // ---- FC head: one thread per row ----
    if (tid < ROWS) {
        const int row = tid;
        float hv[H_DIM];
#pragma unroll
        for (int j = 0; j < H_DIM; j++) hv[j] = sH[j * ROWS + row];

        float o = sB2[0];
        for (int r = 0; r < FC_DIM; r++) {
            float a = sB1[r];
            const float* w = sW1 + r * H_DIM;
#pragma unroll
            for (int j = 0; j < H_DIM; j++) a = fmaf(hv[j], w[j], a);
            o = fmaf(fmaxf(a, 0.0f), sW2[r], o);
        }
        out[b0 + row] = o;
    }
}

extern "C" void kernel_launch(void* const* d_in, const int* in_sizes, int n_in,
                              void* d_out, int out_size)
{
    (void)in_sizes; (void)n_in; (void)out_size;
    const float* x    = (const float*)d_in[0];
    const float* Wih0 = (const float*)d_in[1];
    const float* Whh0 = (const float*)d_in[2];
    const float* bih0 = (const float*)d_in[3];
    const float* bhh0 = (const float*)d_in[4];
    const float* Wih1 = (const float*)d_in[5];
    const float* Whh1 = (const float*)d_in[6];
    const float* bih1 = (const float*)d_in[7];
    const float* bhh1 = (const float*)d_in[8];
    const float* W1   = (const float*)d_in[9];
    const float* b1   = (const float*)d_in[10];
    const float* W2   = (const float*)d_in[11];
    const float* b2   = (const float*)d_in[12];
    float* out = (float*)d_out;

    cudaFuncSetAttribute(rainfall_lstm_kernel,
                         cudaFuncAttributeMaxDynamicSharedMemorySize,
                         SMEM_BYTES);

    rainfall_lstm_kernel<<<NBLK, BLKT, SMEM_BYTES>>>(
        x, Wih0, Whh0, bih0, bhh0, Wih1, Whh1, bih1, bhh1,
        W1, b1, W2, b2, out);
}

// round 9
// speedup vs baseline: 3.0525x; 2.2493x over previous
#include <cuda_runtime.h>
#include <cuda_fp16.h>
#include <cstddef>
#include <cstdint>

#define B_TOTAL 32768
#define T_SEQ   7
#define D_IN    40
#define H_DIM   64
#define FC_DIM  32
#define ROWS    128
#define BLKT    512
#define NBLK    (B_TOTAL / ROWS)   // 256
#define AST     136                // padded stride in halfs (272 B)

// ---------------- smem byte offsets ----------------
#define SM_AH   0                       // A hi  [128][AST] halfs
#define SM_AL   34816                   // A lo
#define SM_BH   69632                   // W hi  [256][AST] halfs
#define SM_BL   139264                  // W lo
#define SM_BIAS 208896                  // 256 fp32
#define SM_FC   209920                  // FC weights fp32
#define SM_TOTAL 218372

// phase-A hidden states fp32: [blk][t][128][64]
__device__ __align__(16) float g_scr[(size_t)NBLK * T_SEQ * ROWS * H_DIM];

// ---------------- helpers ----------------
__device__ __forceinline__ uint32_t smem_u32(const void* p) {
    uint32_t a;
    asm("{ .reg .u64 t; cvta.to.shared.u64 t, %1; cvt.u32.u64 %0, t; }" : "=r"(a) : "l"(p));
    return a;
}
__device__ __forceinline__ void ldsm4(uint32_t r[4], uint32_t addr) {
    asm volatile("ldmatrix.sync.aligned.m8n8.x4.shared.b16 {%0,%1,%2,%3}, [%4];"
        : "=r"(r[0]), "=r"(r[1]), "=r"(r[2]), "=r"(r[3]) : "r"(addr));
}
__device__ __forceinline__ void mma16816(float* c, const uint32_t a[4],
                                         uint32_t b0, uint32_t b1) {
    asm volatile(
        "mma.sync.aligned.m16n8k16.row.col.f32.f16.f16.f32 "
        "{%0,%1,%2,%3}, {%4,%5,%6,%7}, {%8,%9}, {%0,%1,%2,%3};"
        : "+f"(c[0]), "+f"(c[1]), "+f"(c[2]), "+f"(c[3])
        : "r"(a[0]), "r"(a[1]), "r"(a[2]), "r"(a[3]), "r"(b0), "r"(b1));
}
__device__ __forceinline__ float sigf(float x) {
    return __fdividef(1.0f, 1.0f + __expf(-x));
}
__device__ __forceinline__ float tanhf_fast(float x) {
    return __fdividef(2.0f, 1.0f + __expf(-2.0f * x)) - 1.0f;
}
// v = hi + lo (lo unscaled; fp16-normal/denormal for O(1) values)
__device__ __forceinline__ void split16(float v, __half& h, __half& l) {
    h = __float2half_rn(v);
    l = __float2half_rn(v - __half2float(h));
}

// ---------------- weight staging: fp32 -> split fp16 [256][AST] ----------------
__device__ void stage_weights(const float* __restrict__ Wx, int Kx,
                              const float* __restrict__ Wh,
                              const float* __restrict__ bi, const float* __restrict__ bh,
                              unsigned char* sm, int tid)
{
    // zero both W tiles (pad cols) : 2 * 69632 B
    uint4 z = make_uint4(0, 0, 0, 0);
    uint4* zb = (uint4*)(sm + SM_BH);
    for (int i = tid; i < (2 * 69632) / 16; i += BLKT) zb[i] = z;
    __syncthreads();

    for (int e = tid; e < 256 * Kx; e += BLKT) {
        int c = e / Kx, k = e % Kx;
        __half h, l; split16(Wx[e], h, l);
        uint32_t off = (uint32_t)(c * AST + k) * 2;
        *(__half*)(sm + SM_BH + off) = h;
        *(__half*)(sm + SM_BL + off) = l;
    }
    for (int e = tid; e < 256 * H_DIM; e += BLKT) {
        int c = e / H_DIM, k = e % H_DIM;
        __half h, l; split16(Wh[e], h, l);
        uint32_t off = (uint32_t)(c * AST + 64 + k) * 2;
        *(__half*)(sm + SM_BH + off) = h;
        *(__half*)(sm + SM_BL + off) = l;
    }
    float* sB = (float*)(sm + SM_BIAS);
    for (int i = tid; i < 256; i += BLKT) sB[i] = bi[i] + bh[i];
}

// ---------------- one LSTM layer (7 steps) ----------------
template <bool PA>
__device__ void run_phase(unsigned char* sm, uint32_t smb,
                          const float* __restrict__ x, int b0, int blk, int tid)
{
    const int w = tid >> 5, lane = tid & 31;
    const int m0 = (w >> 2) * 32, j0 = (w & 3) * 16;
    const int tig = lane & 3, g8 = lane >> 2;
    const int part = lane >> 3, l = lane & 7;

    // per-thread ldmatrix base addresses (k0 = 0)
    // A: matrix0..3 = (rows 0-7,k0-7),(rows 8-15,k0-7),(rows 0-7,k8-15),(rows 8-15,k8-15)
    const uint32_t aA = smb + SM_AH +
        (uint32_t)(((m0 + (part & 1) * 8 + l) * AST + (part >> 1) * 8) * 2);
    // B (non-trans; W is [n][k] row-major, k contiguous = mma B k-pairs):
    // matrix0..3 = (n j0-7,k0-7),(n j0-7,k8-15),(n j0+8-15,k0-7),(n j0+8-15,k8-15)
    const uint32_t aB = smb + SM_BH +
        (uint32_t)(((j0 + (part >> 1) * 8 + l) * AST + (part & 1) * 8) * 2);
    const float* sBias = (const float*)(sm + SM_BIAS);

    float acc[64];
    float c[16];
#pragma unroll
    for (int i = 0; i < 64; i++) acc[i] = 0.0f;
#pragma unroll
    for (int i = 0; i < 16; i++) c[i] = 0.0f;

    for (int t = 0; t < T_SEQ; t++) {
        // ---- stage this step's x-part into A cols [0, KIN) ----
        if (PA) {
            int row = tid >> 2, q = tid & 3;   // 10 floats each
            const float2* xb = (const float2*)(
                x + ((size_t)(b0 + row) * T_SEQ + t) * D_IN + q * 10);
#pragma unroll
            for (int i = 0; i < 5; i++) {
                float2 v = xb[i];
                __half h0, l0, h1, l1;
                split16(v.x, h0, l0); split16(v.y, h1, l1);
                uint32_t off = (uint32_t)((row * AST + q * 10 + 2 * i) * 2);
                *(__half2*)(sm + SM_AH + off) = __halves2half2(h0, h1);
                *(__half2*)(sm + SM_AL + off) = __halves2half2(l0, l1);
            }
        } else {
            const float2* src = (const float2*)(
                g_scr + ((size_t)blk * T_SEQ + t) * (ROWS * H_DIM));
#pragma unroll
            for (int i = 0; i < 8; i++) {
                int fi = tid + i * BLKT;           // 0..4095 float2
                int row = fi >> 5, jp = fi & 31;
                float2 v = src[fi];
                __half h0, l0, h1, l1;
                split16(v.x, h0, l0); split16(v.y, h1, l1);
                uint32_t off = (uint32_t)((row * AST + 2 * jp) * 2);
                *(__half2*)(sm + SM_AH + off) = __halves2half2(h0, h1);
                *(__half2*)(sm + SM_AL + off) = __halves2half2(l0, l1);
            }
        }
        __syncthreads();

        // ---- tensor-core GEMM: acc += Ah@Bh + Ah@Bl + Al@Bh ----
#pragma unroll
        for (int ks = 0; ks < 8; ks++) {
            if (PA && ks == 3) continue;       // cols 48..63 are zero pad
            const uint32_t kb = (uint32_t)ks * 32;   // 16 halfs = 32 B
            uint32_t ah[2][4], al[2][4];
            ldsm4(ah[0], aA + kb);
            ldsm4(ah[1], aA + 16 * AST * 2 + kb);
            ldsm4(al[0], aA + (SM_AL - SM_AH) + kb);
            ldsm4(al[1], aA + (SM_AL - SM_AH) + 16 * AST * 2 + kb);
#pragma unroll
            for (int g4 = 0; g4 < 4; g4++) {
                uint32_t bh[4], bl[4];
                ldsm4(bh, aB + (uint32_t)g4 * 64 * AST * 2 + kb);
                ldsm4(bl, aB + (SM_BL - SM_BH) + (uint32_t)g4 * 64 * AST * 2 + kb);
#pragma unroll
                for (int mt = 0; mt < 2; mt++) {
                    float* a0 = &acc[((g4 * 2 + 0) * 2 + mt) * 4];
                    float* a1 = &acc[((g4 * 2 + 1) * 2 + mt) * 4];
                    mma16816(a0, ah[mt], bh[0], bh[1]);
                    mma16816(a1, ah[mt], bh[2], bh[3]);
                    mma16816(a0, ah[mt], bl[0], bl[1]);
                    mma16816(a1, ah[mt], bl[2], bl[3]);
                    mma16816(a0, al[mt], bh[0], bh[1]);
                    mma16816(a1, al[mt], bh[2], bh[3]);
                }
            }
        }
        __syncthreads();   // all ldmatrix reads complete before h rewrite

        // ---- epilogue: gates -> c, h ----
        const bool last = (!PA) && (t == T_SEQ - 1);
#pragma unroll
        for (int mt = 0; mt < 2; mt++)
#pragma unroll
        for (int rr = 0; rr < 2; rr++)
#pragma unroll
        for (int nt = 0; nt < 2; nt++) {
            const int jj = j0 + nt * 8 + 2 * tig;
            float2 bi = *(const float2*)(sBias + jj);
            float2 bf = *(const float2*)(sBias + 64 + jj);
            float2 bg = *(const float2*)(sBias + 128 + jj);
            float2 bo = *(const float2*)(sBias + 192 + jj);
            float hv[2];
#pragma unroll
            for (int e = 0; e < 2; e++) {
                float pi = acc[((0 * 2 + nt) * 2 + mt) * 4 + rr * 2 + e] + (e ? bi.y : bi.x);
                float pf = acc[((1 * 2 + nt) * 2 + mt) * 4 + rr * 2 + e] + (e ? bf.y : bf.x);
                float pg = acc[((2 * 2 + nt) * 2 + mt) * 4 + rr * 2 + e] + (e ? bg.y : bg.x);
                float po = acc[((3 * 2 + nt) * 2 + mt) * 4 + rr * 2 + e] + (e ? bo.y : bo.x);
                float ig = sigf(pi), fg = sigf(pf);
                float gg = tanhf_fast(pg), og = sigf(po);
                int ci = ((mt * 2 + rr) * 2 + nt) * 2 + e;
                float cn = fmaf(fg, c[ci], ig * gg);
                c[ci] = cn;
                hv[e] = og * tanhf_fast(cn);
            }
            const int row = m0 + mt * 16 + rr * 8 + g8;
            if (last) {
                *(float2*)((float*)(sm + SM_AL) + row * 64 + jj) =
                    make_float2(hv[0], hv[1]);
            } else {
                __half h0, l0, h1, l1;
                split16(hv[0], h0, l0); split16(hv[1], h1, l1);
                uint32_t off = (uint32_t)((row * AST + 64 + jj) * 2);
                *(__half2*)(sm + SM_AH + off) = __halves2half2(h0, h1);
                *(__half2*)(sm + SM_AL + off) = __halves2half2(l0, l1);
                if (PA)
                    *(float2*)(g_scr + (((size_t)blk * T_SEQ + t) * ROWS + row) * 64 + jj) =
                        make_float2(hv[0], hv[1]);
            }
            // clear acc for next step
#pragma unroll
            for (int g4 = 0; g4 < 4; g4++) {
                acc[((g4 * 2 + nt) * 2 + mt) * 4 + rr * 2 + 0] = 0.0f;
                acc[((g4 * 2 + nt) * 2 + mt) * 4 + rr * 2 + 1] = 0.0f;
            }
        }
        // next iteration: staging writes x cols, then __syncthreads orders
        // these h writes before the next ldmatrix reads.
    }
}

__global__ void __launch_bounds__(BLKT, 1)
rainfall_lstm_hmma_kernel(
    const float* __restrict__ x,
    const float* __restrict__ Wih0, const float* __restrict__ Whh0,
    const float* __restrict__ bih0, const float* __restrict__ bhh0,
    const float* __restrict__ Wih1, const float* __restrict__ Whh1,
    const float* __restrict__ bih1, const float* __restrict__ bhh1,
    const float* __restrict__ W1, const float* __restrict__ b1,
    const float* __restrict__ W2, const float* __restrict__ b2,
    float* __restrict__ out)
{
    extern __shared__ unsigned char sm[];
    const uint32_t smb = smem_u32(sm);
    const int tid = threadIdx.x;
    const int blk = blockIdx.x;
    const int b0 = blk * ROWS;

    // ---- phase A setup ----
    stage_weights(Wih0, D_IN, Whh0, bih0, bhh0, sm, tid);
    {   // zero A hi+lo (covers x pad cols 40..63 and h0 = 0)
        uint4 z = make_uint4(0, 0, 0, 0);
        uint4* za = (uint4*)(sm + SM_AH);
        for (int i = tid; i < (2 * 34816) / 16; i += BLKT) za[i] = z;
    }
    __syncthreads();
    run_phase<true>(sm, smb, x, b0, blk, tid);
    __syncthreads();   // phase-A epilogue writes done before W restage

    // ---- phase B setup ----
    stage_weights(Wih1, H_DIM, Whh1, bih1, bhh1, sm, tid);
    {   // zero A hi+lo (h0 = 0 for layer 1)
        uint4 z = make_uint4(0, 0, 0, 0);
        uint4* za = (uint4*)(sm + SM_AH);
        for (int i = tid; i < (2 * 34816) / 16; i += BLKT) za[i] = z;
    }
    {   // FC weights
        float* fw = (float*)(sm + SM_FC);
        for (int i = tid; i < FC_DIM * H_DIM; i += BLKT) fw[i] = W1[i];
        if (tid < FC_DIM) { fw[2048 + tid] = b1[tid]; fw[2080 + tid] = W2[tid]; }
        if (tid == 0) fw[2112] = b2[0];
    }
    __syncthreads();
    run_phase<false>(sm, smb, nullptr, b0, blk, tid);
    __syncthreads();   // sFC (in SM_AL) complete

    // ---- FC head: one thread per row ----
    if (tid < ROWS) {
        const float* sFC = (const float*)(sm + SM_AL);
        const float* fw = (const float*)(sm + SM_FC);
        float hv[H_DIM];
#pragma unroll
        for (int j = 0; j < H_DIM; j++) hv[j] = sFC[tid * 64 + j];
        float o = fw[2112];
#pragma unroll
        for (int r = 0; r < FC_DIM; r++) {
            float a = fw[2048 + r];
            const float* wr = fw + r * H_DIM;
#pragma unroll
            for (int j = 0; j < H_DIM; j++) a = fmaf(hv[j], wr[j], a);
            o = fmaf(fmaxf(a, 0.0f), fw[2080 + r], o);
        }
        out[b0 + tid] = o;
    }
}

extern "C" void kernel_launch(void* const* d_in, const int* in_sizes, int n_in,
                              void* d_out, int out_size)
{
    (void)in_sizes; (void)n_in; (void)out_size;
    const float* x    = (const float*)d_in[0];
    const float* Wih0 = (const float*)d_in[1];
    const float* Whh0 = (const float*)d_in[2];
    const float* bih0 = (const float*)d_in[3];
    const float* bhh0 = (const float*)d_in[4];
    const float* Wih1 = (const float*)d_in[5];
    const float* Whh1 = (const float*)d_in[6];
    const float* bih1 = (const float*)d_in[7];
    const float* bhh1 = (const float*)d_in[8];
    const float* W1   = (const float*)d_in[9];
    const float* b1   = (const float*)d_in[10];
    const float* W2   = (const float*)d_in[11];
    const float* b2   = (const float*)d_in[12];
    float* out = (float*)d_out;

    cudaFuncSetAttribute(rainfall_lstm_hmma_kernel,
                         cudaFuncAttributeMaxDynamicSharedMemorySize,
                         SM_TOTAL);

    rainfall_lstm_hmma_kernel<<<NBLK, BLKT, SM_TOTAL>>>(
        x, Wih0, Whh0, bih0, bhh0, Wih1, Whh1, bih1, bhh1,
        W1, b1, W2, b2, out);
}